// round 11
// baseline (speedup 1.0000x reference)
#include <cuda_runtime.h>

// EthanolSNN: 3-layer LIF SNN inference. T=256, B=8192, D=64, H1=28, H2=14.
// Output mem3 [T, B, 1] fp32.
//
// Two-kernel split:
//  K1: layer-1 accumulations for ALL (t,e) at full occupancy (no recurrence).
//      NEW (r10): one thread per element-timestep, x staged via shared memory
//      (coalesced full-sector loads, no duplication, conflict-free LDS).
//      Serial ascending-k fma2 chains -> BIT-IDENTICAL numerics.
//  K2: sequential LIF recurrence — UNCHANGED from round 8 (measured 213us).
//
// Numerics BIT-IDENTICAL to round-5 passing kernel (rel_err 7.44e-4):
//  - dot products: single serial ascending-index FMA chain per neuron
//  - bias added as separate rounded add after the chain
//  - LIF: RN(RN(RN(b*m)+cur)-reset), reset subtract via exact-product fma
//  - threshold m>1 == (m-1)>0 in fp32

typedef unsigned long long ull_t;

#define TT 256
#define BB 8192
#define DD 64
#define HH1 28
#define HH2 14

// scratch: [et][16] ull; et = t*BB+e; half q uses slots [q*8 .. q*8+6]
#define SCRATCH_ULLS (256ULL * 8192ULL * 16ULL)
__device__ ull_t g_cur1[SCRATCH_ULLS];   // 268 MB, module-load allocated

__device__ __forceinline__ ull_t pk2(float lo, float hi) {
    ull_t r;
    asm("mov.b64 %0, {%1, %2};" : "=l"(r) : "f"(lo), "f"(hi));
    return r;
}
__device__ __forceinline__ void upk2(ull_t v, float& lo, float& hi) {
    asm("mov.b64 {%0, %1}, %2;" : "=f"(lo), "=f"(hi) : "l"(v));
}
__device__ __forceinline__ ull_t fma2(ull_t a, ull_t b, ull_t c) {
    ull_t d;
    asm("fma.rn.f32x2 %0, %1, %2, %3;" : "=l"(d) : "l"(a), "l"(b), "l"(c));
    return d;
}
__device__ __forceinline__ ull_t add2(ull_t a, ull_t b) {
    ull_t d;
    asm("add.rn.f32x2 %0, %1, %2;" : "=l"(d) : "l"(a), "l"(b));
    return d;
}
__device__ __forceinline__ ull_t mul2(ull_t a, ull_t b) {
    ull_t d;
    asm("mul.rn.f32x2 %0, %1, %2;" : "=l"(d) : "l"(a), "l"(b));
    return d;
}

// ============================================================================
// Kernel 1 (rebuilt): layer-1 accumulation, one thread per element-timestep.
// Block = 128 threads = 128 consecutive et. x rows staged via smem:
//  - stage loads: fully coalesced LDG.128 (consecutive lanes -> consecutive 16B)
//  - smem row stride 65 floats -> compute LDS.32 bank = (tid+k)%32, conflict-free
//  - weight LDS.128 warp-uniform -> broadcast
// 14 serial ascending-k fma2 chains per thread (bit-identical to round 5/8).
// ============================================================================
__global__ void __launch_bounds__(128)
snn_layer1_kernel(const float* __restrict__ x, const float* __restrict__ W1)
{
    __shared__ __align__(16) ull_t w1p[DD * 16];   // [k][16]: pairs j=0..13, pad 14,15 (8KB)
    __shared__ float xs[128 * 65];                 // 128 rows, stride 65 (33.3KB)

    const int tid = threadIdx.x;

    // ---- pack W1 pairs: w1p[k*16+j] = {W1[2j][k], W1[2j+1][k]} ----
    for (int idx = tid; idx < DD * 16; idx += 128) {
        int k = idx >> 4, j = idx & 15;
        float lo = 0.f, hi = 0.f;
        if (j < 14) {
            lo = W1[(2 * j)     * DD + k];
            hi = W1[(2 * j + 1) * DD + k];
        }
        w1p[idx] = pk2(lo, hi);
    }

    // ---- stage this block's 128 x rows (contiguous 32KB of x) ----
    const float4* xg = (const float4*)(x + (size_t)blockIdx.x * (128 * DD));
    #pragma unroll
    for (int r = 0; r < 16; r++) {
        int pos = tid + 128 * r;            // float4 index within the 2048-float4 tile
        float4 v = __ldcs(xg + pos);
        int row = pos >> 4;                 // 0..127
        int col = (pos & 15) * 4;           // 0..60
        float* dst = &xs[row * 65 + col];
        dst[0] = v.x; dst[1] = v.y; dst[2] = v.z; dst[3] = v.w;
    }
    __syncthreads();

    // ---- 14 serial ascending-k fma2 chains (exact round-5 numerics) ----
    ull_t acc[14];
    #pragma unroll
    for (int j = 0; j < 14; j++) acc[j] = 0ULL;

    const float* xrow = &xs[tid * 65];
    #pragma unroll 8
    for (int k = 0; k < DD; k++) {
        float xv = xrow[k];
        ull_t xx = pk2(xv, xv);
        const ulonglong2* wr = (const ulonglong2*)(w1p + k * 16);
        ulonglong2 w01 = wr[0], w23 = wr[1], w45 = wr[2], w67 = wr[3],
                   w89 = wr[4], wab = wr[5], wcd = wr[6];
        acc[0]  = fma2(xx, w01.x, acc[0]);
        acc[1]  = fma2(xx, w01.y, acc[1]);
        acc[2]  = fma2(xx, w23.x, acc[2]);
        acc[3]  = fma2(xx, w23.y, acc[3]);
        acc[4]  = fma2(xx, w45.x, acc[4]);
        acc[5]  = fma2(xx, w45.y, acc[5]);
        acc[6]  = fma2(xx, w67.x, acc[6]);
        acc[7]  = fma2(xx, w67.y, acc[7]);
        acc[8]  = fma2(xx, w89.x, acc[8]);
        acc[9]  = fma2(xx, w89.y, acc[9]);
        acc[10] = fma2(xx, wab.x, acc[10]);
        acc[11] = fma2(xx, wab.y, acc[11]);
        acc[12] = fma2(xx, wcd.x, acc[12]);
        acc[13] = fma2(xx, wcd.y, acc[13]);
    }

    // ---- store to scratch [et][16]: slots 0..6 = pairs 0..6 (q=0 half),
    //      slots 8..14 = pairs 7..13 (q=1 half); aligned STG.128 ----
    const size_t et = (size_t)blockIdx.x * 128 + tid;
    ulonglong2* d = (ulonglong2*)(g_cur1 + et * 16);
    ulonglong2 p;
    p.x = acc[0];  p.y = acc[1];  d[0] = p;
    p.x = acc[2];  p.y = acc[3];  d[1] = p;
    p.x = acc[4];  p.y = acc[5];  d[2] = p;
    p.x = acc[6];  p.y = 0ULL;    d[3] = p;
    p.x = acc[7];  p.y = acc[8];  d[4] = p;
    p.x = acc[9];  p.y = acc[10]; d[5] = p;
    p.x = acc[11]; p.y = acc[12]; d[6] = p;
    p.x = acc[13]; p.y = 0ULL;    d[7] = p;
}

// ============================================================================
// Kernel 2: LIF recurrence (round-8, UNCHANGED — measured 213us).
// ============================================================================
__global__ void __launch_bounds__(64, 1)
snn_recur_kernel(const float* __restrict__ b1,
                 const float* __restrict__ W2, const float* __restrict__ b2,
                 const float* __restrict__ W3, const float* __restrict__ b3,
                 float* __restrict__ out)
{
    __shared__ __align__(16) ull_t w2p[HH1 * 8];
    __shared__ ull_t b1p[14];
    __shared__ ull_t b2p[8];
    __shared__ float w3s[14];
    __shared__ float b3s;

    const int tid  = threadIdx.x;
    const int lane = tid & 31;
    const int warp = tid >> 5;
    const int p    = lane >> 1;            // element slot within warp (0..15)
    const int q    = lane & 1;             // neuron-half owner
    const int e    = blockIdx.x * 32 + warp * 16 + p;

    for (int idx = tid; idx < HH1 * 8; idx += 64) {
        int i = idx >> 3, r = idx & 7, qq = r >> 2, m = r & 3;
        float lo = (2 * m     < 7) ? W2[(qq * 7 + 2 * m)     * HH1 + i] : 0.f;
        float hi = (2 * m + 1 < 7) ? W2[(qq * 7 + 2 * m + 1) * HH1 + i] : 0.f;
        w2p[idx] = pk2(lo, hi);
    }
    if (tid < 14) {
        int qq = tid / 7, ii = tid - qq * 7;
        b1p[tid] = pk2(b1[qq * 14 + 2 * ii], b1[qq * 14 + 2 * ii + 1]);
        w3s[tid] = W3[tid];
    }
    if (tid < 8) {
        int qq = tid >> 2, m = tid & 3;
        float lo = (2 * m     < 7) ? b2[qq * 7 + 2 * m]     : 0.f;
        float hi = (2 * m + 1 < 7) ? b2[qq * 7 + 2 * m + 1] : 0.f;
        b2p[tid] = pk2(lo, hi);
    }
    if (tid == 0) b3s = b3[0];
    __syncthreads();

    ull_t b1own[7], b2own[4];
    #pragma unroll
    for (int i = 0; i < 7; i++) b1own[i] = b1p[q * 7 + i];
    #pragma unroll
    for (int m = 0; m < 4; m++) b2own[m] = b2p[q * 4 + m];

    const ull_t BETA2 = pk2(0.9f, 0.9f);
    const ull_t NEG2  = pk2(-1.0f, -1.0f);

    ull_t m1v[7], m2v[4];
    #pragma unroll
    for (int i = 0; i < 7; i++) m1v[i] = 0ULL;
    #pragma unroll
    for (int m = 0; m < 4; m++) m2v[m] = 0ULL;
    float m3 = 0.0f;

    const ull_t* cbase = g_cur1 + (size_t)e * 16 + q * 8;
    const size_t cstep = (size_t)BB * 16;

    #pragma unroll 1
    for (int t = 0; t < TT; t++) {
        const ulonglong2* cp = (const ulonglong2*)(cbase + (size_t)t * cstep);
        ulonglong2 c0 = cp[0], c1 = cp[1], c2 = cp[2], c3v = cp[3];
        ull_t acc[7] = {c0.x, c0.y, c1.x, c1.y, c2.x, c2.y, c3v.x};

        if (t + 1 < TT) {
            const char* pf = (const char*)(cbase + (size_t)(t + 1) * cstep);
            asm volatile("prefetch.global.L2 [%0];" :: "l"(pf));
        }

        // ---- LIF layer 1 (exact rounding sequence) ----
        float s1own[14];
        #pragma unroll
        for (int i = 0; i < 7; i++) {
            ull_t mold = m1v[i];
            float mlo, mhi;
            upk2(mold, mlo, mhi);
            float rlo = (mlo > 1.0f) ? 1.0f : 0.0f;
            float rhi = (mhi > 1.0f) ? 1.0f : 0.0f;
            ull_t cur = add2(acc[i], b1own[i]);
            ull_t mb  = mul2(BETA2, mold);
            ull_t tmp = add2(mb, cur);
            ull_t mn  = fma2(pk2(rlo, rhi), NEG2, tmp);
            m1v[i] = mn;
            float nlo, nhi;
            upk2(mn, nlo, nhi);
            s1own[2 * i]     = (nlo > 1.0f) ? 1.0f : 0.0f;
            s1own[2 * i + 1] = (nhi > 1.0f) ? 1.0f : 0.0f;
        }

        // ---- exchange spike halves across the pair ----
        float s1o[14];
        #pragma unroll
        for (int i = 0; i < 7; i++) {
            ull_t sp = pk2(s1own[2 * i], s1own[2 * i + 1]);
            ull_t g  = __shfl_xor_sync(0xFFFFFFFFu, sp, 1);
            upk2(g, s1o[2 * i], s1o[2 * i + 1]);
        }
        float s1all[28];
        #pragma unroll
        for (int i = 0; i < 14; i++) {
            s1all[i]      = q ? s1o[i]   : s1own[i];
            s1all[14 + i] = q ? s1own[i] : s1o[i];
        }

        // ---- layer 2: serial ascending-i FMA chains ----
        ull_t a2[4];
        #pragma unroll
        for (int m = 0; m < 4; m++) a2[m] = 0ULL;
        #pragma unroll
        for (int i = 0; i < HH1; i++) {
            ull_t ss = pk2(s1all[i], s1all[i]);
            const ulonglong2* wr = (const ulonglong2*)(w2p + (size_t)i * 8 + q * 4);
            ulonglong2 u0 = wr[0], u1 = wr[1];
            a2[0] = fma2(ss, u0.x, a2[0]);
            a2[1] = fma2(ss, u0.y, a2[1]);
            a2[2] = fma2(ss, u1.x, a2[2]);
            a2[3] = fma2(ss, u1.y, a2[3]);
        }

        // ---- LIF layer 2 ----
        float s2own[8];
        #pragma unroll
        for (int m = 0; m < 4; m++) {
            ull_t mold = m2v[m];
            float mlo, mhi;
            upk2(mold, mlo, mhi);
            float rlo = (mlo > 1.0f) ? 1.0f : 0.0f;
            float rhi = (mhi > 1.0f) ? 1.0f : 0.0f;
            ull_t cur = add2(a2[m], b2own[m]);
            ull_t mb  = mul2(BETA2, mold);
            ull_t tmp = add2(mb, cur);
            ull_t mn  = fma2(pk2(rlo, rhi), NEG2, tmp);
            m2v[m] = mn;
            float nlo, nhi;
            upk2(mn, nlo, nhi);
            s2own[2 * m]     = (nlo > 1.0f) ? 1.0f : 0.0f;
            s2own[2 * m + 1] = (nhi > 1.0f) ? 1.0f : 0.0f;
        }

        // ---- exchange s2 halves ----
        float s2o[8];
        #pragma unroll
        for (int m = 0; m < 4; m++) {
            ull_t sp = pk2(s2own[2 * m], s2own[2 * m + 1]);
            ull_t g  = __shfl_xor_sync(0xFFFFFFFFu, sp, 1);
            upk2(g, s2o[2 * m], s2o[2 * m + 1]);
        }
        float s2all[14];
        #pragma unroll
        for (int i = 0; i < 7; i++) {
            s2all[i]     = q ? s2o[i]   : s2own[i];
            s2all[7 + i] = q ? s2own[i] : s2o[i];
        }

        // ---- layer 3 + LIF 3 ----
        float c3 = 0.0f;
        #pragma unroll
        for (int i = 0; i < HH2; i++) c3 = fmaf(s2all[i], w3s[i], c3);
        float cur3 = __fadd_rn(c3, b3s);

        float r3  = (m3 > 1.0f) ? 1.0f : 0.0f;
        float mb3 = __fmul_rn(0.9f, m3);
        float t3  = __fadd_rn(mb3, cur3);
        m3 = __fsub_rn(t3, r3);

        if (q == 0) out[(size_t)t * BB + e] = m3;
    }
}

extern "C" void kernel_launch(void* const* d_in, const int* in_sizes, int n_in,
                              void* d_out, int out_size) {
    const float* x  = (const float*)d_in[0];
    const float* W1 = (const float*)d_in[1];
    const float* b1 = (const float*)d_in[2];
    const float* W2 = (const float*)d_in[3];
    const float* b2 = (const float*)d_in[4];
    const float* W3 = (const float*)d_in[5];
    const float* b3 = (const float*)d_in[6];
    float* out = (float*)d_out;

    // K1: 2,097,152 element-timesteps, 1 per thread -> 16384 blocks x 128
    snn_layer1_kernel<<<16384, 128>>>(x, W1);

    // K2: 8192 elements, 32 per block (64 threads = 2 threads per element)
    snn_recur_kernel<<<256, 64>>>(b1, W2, b2, W3, b3, out);
}

// round 12
// speedup vs baseline: 1.1520x; 1.1520x over previous
#include <cuda_runtime.h>

// EthanolSNN: 3-layer LIF SNN inference. T=256, B=8192, D=64, H1=28, H2=14.
// Output mem3 [T, B, 1] fp32.
//
// Two-kernel split:
//  K1: layer-1 accumulations for ALL (t,e), one thread per element-timestep,
//      x staged via smem (coalesced, conflict-free). r11: k-loop unroll 2
//      (r10's unroll 8 spilled ~100 regs to local -> 376us).
//  K2: sequential LIF recurrence. r11: register double-buffer of the acc
//      loads across timesteps (hides the L2-hit latency behind step-t compute).
//
// Numerics BIT-IDENTICAL to round-5 passing kernel (rel_err 7.44e-4):
//  - dot products: single serial ascending-index FMA chain per neuron
//  - bias added as separate rounded add after the chain
//  - LIF: RN(RN(RN(b*m)+cur)-reset), reset subtract via exact-product fma
//  - threshold m>1 == (m-1)>0 in fp32

typedef unsigned long long ull_t;

#define TT 256
#define BB 8192
#define DD 64
#define HH1 28
#define HH2 14

// scratch: [et][16] ull; et = t*BB+e; half q uses slots [q*8 .. q*8+6]
#define SCRATCH_ULLS (256ULL * 8192ULL * 16ULL)
__device__ ull_t g_cur1[SCRATCH_ULLS];   // 268 MB, module-load allocated

__device__ __forceinline__ ull_t pk2(float lo, float hi) {
    ull_t r;
    asm("mov.b64 %0, {%1, %2};" : "=l"(r) : "f"(lo), "f"(hi));
    return r;
}
__device__ __forceinline__ void upk2(ull_t v, float& lo, float& hi) {
    asm("mov.b64 {%0, %1}, %2;" : "=f"(lo), "=f"(hi) : "l"(v));
}
__device__ __forceinline__ ull_t fma2(ull_t a, ull_t b, ull_t c) {
    ull_t d;
    asm("fma.rn.f32x2 %0, %1, %2, %3;" : "=l"(d) : "l"(a), "l"(b), "l"(c));
    return d;
}
__device__ __forceinline__ ull_t add2(ull_t a, ull_t b) {
    ull_t d;
    asm("add.rn.f32x2 %0, %1, %2;" : "=l"(d) : "l"(a), "l"(b));
    return d;
}
__device__ __forceinline__ ull_t mul2(ull_t a, ull_t b) {
    ull_t d;
    asm("mul.rn.f32x2 %0, %1, %2;" : "=l"(d) : "l"(a), "l"(b));
    return d;
}

// ============================================================================
// Kernel 1: layer-1 accumulation, one thread per element-timestep.
// Block = 128 threads = 128 consecutive et. x staged via smem:
//  - stage loads: fully coalesced LDG.128
//  - smem row stride 65 floats -> compute LDS.32 conflict-free
//  - weight LDS.128 warp-uniform -> broadcast
// k-loop unroll 2 to keep live registers < ~100 (no spill).
// ============================================================================
__global__ void __launch_bounds__(128)
snn_layer1_kernel(const float* __restrict__ x, const float* __restrict__ W1)
{
    __shared__ __align__(16) ull_t w1p[DD * 16];   // [k][16]: pairs j=0..13, pad (8KB)
    __shared__ float xs[128 * 65];                 // 128 rows, stride 65 (33.3KB)

    const int tid = threadIdx.x;

    // ---- pack W1 pairs: w1p[k*16+j] = {W1[2j][k], W1[2j+1][k]} ----
    for (int idx = tid; idx < DD * 16; idx += 128) {
        int k = idx >> 4, j = idx & 15;
        float lo = 0.f, hi = 0.f;
        if (j < 14) {
            lo = W1[(2 * j)     * DD + k];
            hi = W1[(2 * j + 1) * DD + k];
        }
        w1p[idx] = pk2(lo, hi);
    }

    // ---- stage this block's 128 x rows (contiguous 32KB of x) ----
    const float4* xg = (const float4*)(x + (size_t)blockIdx.x * (128 * DD));
    #pragma unroll
    for (int r = 0; r < 16; r++) {
        int pos = tid + 128 * r;            // float4 index within the 2048-float4 tile
        float4 v = __ldcs(xg + pos);
        int row = pos >> 4;                 // 0..127
        int col = (pos & 15) * 4;           // 0..60
        float* dst = &xs[row * 65 + col];
        dst[0] = v.x; dst[1] = v.y; dst[2] = v.z; dst[3] = v.w;
    }
    __syncthreads();

    // ---- 14 serial ascending-k fma2 chains (exact round-5 numerics) ----
    ull_t acc[14];
    #pragma unroll
    for (int j = 0; j < 14; j++) acc[j] = 0ULL;

    const float* xrow = &xs[tid * 65];
    #pragma unroll 2
    for (int k = 0; k < DD; k++) {
        float xv = xrow[k];
        ull_t xx = pk2(xv, xv);
        const ulonglong2* wr = (const ulonglong2*)(w1p + k * 16);
        ulonglong2 w01 = wr[0], w23 = wr[1], w45 = wr[2], w67 = wr[3],
                   w89 = wr[4], wab = wr[5], wcd = wr[6];
        acc[0]  = fma2(xx, w01.x, acc[0]);
        acc[1]  = fma2(xx, w01.y, acc[1]);
        acc[2]  = fma2(xx, w23.x, acc[2]);
        acc[3]  = fma2(xx, w23.y, acc[3]);
        acc[4]  = fma2(xx, w45.x, acc[4]);
        acc[5]  = fma2(xx, w45.y, acc[5]);
        acc[6]  = fma2(xx, w67.x, acc[6]);
        acc[7]  = fma2(xx, w67.y, acc[7]);
        acc[8]  = fma2(xx, w89.x, acc[8]);
        acc[9]  = fma2(xx, w89.y, acc[9]);
        acc[10] = fma2(xx, wab.x, acc[10]);
        acc[11] = fma2(xx, wab.y, acc[11]);
        acc[12] = fma2(xx, wcd.x, acc[12]);
        acc[13] = fma2(xx, wcd.y, acc[13]);
    }

    // ---- store to scratch [et][16]: slots 0..6 = pairs 0..6 (q=0 half),
    //      slots 8..14 = pairs 7..13 (q=1 half); aligned STG.128 ----
    const size_t et = (size_t)blockIdx.x * 128 + tid;
    ulonglong2* d = (ulonglong2*)(g_cur1 + et * 16);
    ulonglong2 p;
    p.x = acc[0];  p.y = acc[1];  d[0] = p;
    p.x = acc[2];  p.y = acc[3];  d[1] = p;
    p.x = acc[4];  p.y = acc[5];  d[2] = p;
    p.x = acc[6];  p.y = 0ULL;    d[3] = p;
    p.x = acc[7];  p.y = acc[8];  d[4] = p;
    p.x = acc[9];  p.y = acc[10]; d[5] = p;
    p.x = acc[11]; p.y = acc[12]; d[6] = p;
    p.x = acc[13]; p.y = 0ULL;    d[7] = p;
}

// ============================================================================
// Kernel 2: LIF recurrence. r11: register double-buffered acc loads — the
// 4 LDG.128 for step t+1 issue before step t's compute, consumed next iter.
// ============================================================================
__global__ void __launch_bounds__(64, 1)
snn_recur_kernel(const float* __restrict__ b1,
                 const float* __restrict__ W2, const float* __restrict__ b2,
                 const float* __restrict__ W3, const float* __restrict__ b3,
                 float* __restrict__ out)
{
    __shared__ __align__(16) ull_t w2p[HH1 * 8];
    __shared__ ull_t b1p[14];
    __shared__ ull_t b2p[8];
    __shared__ float w3s[14];
    __shared__ float b3s;

    const int tid  = threadIdx.x;
    const int lane = tid & 31;
    const int warp = tid >> 5;
    const int p    = lane >> 1;            // element slot within warp (0..15)
    const int q    = lane & 1;             // neuron-half owner
    const int e    = blockIdx.x * 32 + warp * 16 + p;

    for (int idx = tid; idx < HH1 * 8; idx += 64) {
        int i = idx >> 3, r = idx & 7, qq = r >> 2, m = r & 3;
        float lo = (2 * m     < 7) ? W2[(qq * 7 + 2 * m)     * HH1 + i] : 0.f;
        float hi = (2 * m + 1 < 7) ? W2[(qq * 7 + 2 * m + 1) * HH1 + i] : 0.f;
        w2p[idx] = pk2(lo, hi);
    }
    if (tid < 14) {
        int qq = tid / 7, ii = tid - qq * 7;
        b1p[tid] = pk2(b1[qq * 14 + 2 * ii], b1[qq * 14 + 2 * ii + 1]);
        w3s[tid] = W3[tid];
    }
    if (tid < 8) {
        int qq = tid >> 2, m = tid & 3;
        float lo = (2 * m     < 7) ? b2[qq * 7 + 2 * m]     : 0.f;
        float hi = (2 * m + 1 < 7) ? b2[qq * 7 + 2 * m + 1] : 0.f;
        b2p[tid] = pk2(lo, hi);
    }
    if (tid == 0) b3s = b3[0];
    __syncthreads();

    ull_t b1own[7], b2own[4];
    #pragma unroll
    for (int i = 0; i < 7; i++) b1own[i] = b1p[q * 7 + i];
    #pragma unroll
    for (int m = 0; m < 4; m++) b2own[m] = b2p[q * 4 + m];

    const ull_t BETA2 = pk2(0.9f, 0.9f);
    const ull_t NEG2  = pk2(-1.0f, -1.0f);

    ull_t m1v[7], m2v[4];
    #pragma unroll
    for (int i = 0; i < 7; i++) m1v[i] = 0ULL;
    #pragma unroll
    for (int m = 0; m < 4; m++) m2v[m] = 0ULL;
    float m3 = 0.0f;

    const ull_t* cbase = g_cur1 + (size_t)e * 16 + q * 8;
    const size_t cstep = (size_t)BB * 16;

    // ---- preload acc for t=0 ----
    ulonglong2 c0, c1, c2, c3v;
    {
        const ulonglong2* cp = (const ulonglong2*)cbase;
        c0 = cp[0]; c1 = cp[1]; c2 = cp[2]; c3v = cp[3];
    }

    #pragma unroll 1
    for (int t = 0; t < TT; t++) {
        // ---- issue next step's acc loads NOW (consumed next iteration) ----
        const int tn = (t + 1 < TT) ? (t + 1) : t;
        const ulonglong2* np = (const ulonglong2*)(cbase + (size_t)tn * cstep);
        ulonglong2 n0 = np[0], n1 = np[1], n2 = np[2], n3 = np[3];

        // ---- prefetch t+2 into L2 so next iteration's LDG is an L2 hit ----
        if (t + 2 < TT) {
            const char* pf = (const char*)(cbase + (size_t)(t + 2) * cstep);
            asm volatile("prefetch.global.L2 [%0];" :: "l"(pf));
        }

        ull_t acc[7] = {c0.x, c0.y, c1.x, c1.y, c2.x, c2.y, c3v.x};

        // ---- LIF layer 1 (exact rounding sequence) ----
        float s1own[14];
        #pragma unroll
        for (int i = 0; i < 7; i++) {
            ull_t mold = m1v[i];
            float mlo, mhi;
            upk2(mold, mlo, mhi);
            float rlo = (mlo > 1.0f) ? 1.0f : 0.0f;
            float rhi = (mhi > 1.0f) ? 1.0f : 0.0f;
            ull_t cur = add2(acc[i], b1own[i]);
            ull_t mb  = mul2(BETA2, mold);
            ull_t tmp = add2(mb, cur);
            ull_t mn  = fma2(pk2(rlo, rhi), NEG2, tmp);
            m1v[i] = mn;
            float nlo, nhi;
            upk2(mn, nlo, nhi);
            s1own[2 * i]     = (nlo > 1.0f) ? 1.0f : 0.0f;
            s1own[2 * i + 1] = (nhi > 1.0f) ? 1.0f : 0.0f;
        }

        // ---- exchange spike halves across the pair ----
        float s1o[14];
        #pragma unroll
        for (int i = 0; i < 7; i++) {
            ull_t sp = pk2(s1own[2 * i], s1own[2 * i + 1]);
            ull_t g  = __shfl_xor_sync(0xFFFFFFFFu, sp, 1);
            upk2(g, s1o[2 * i], s1o[2 * i + 1]);
        }
        float s1all[28];
        #pragma unroll
        for (int i = 0; i < 14; i++) {
            s1all[i]      = q ? s1o[i]   : s1own[i];
            s1all[14 + i] = q ? s1own[i] : s1o[i];
        }

        // ---- layer 2: serial ascending-i FMA chains ----
        ull_t a2[4];
        #pragma unroll
        for (int m = 0; m < 4; m++) a2[m] = 0ULL;
        #pragma unroll
        for (int i = 0; i < HH1; i++) {
            ull_t ss = pk2(s1all[i], s1all[i]);
            const ulonglong2* wr = (const ulonglong2*)(w2p + (size_t)i * 8 + q * 4);
            ulonglong2 u0 = wr[0], u1 = wr[1];
            a2[0] = fma2(ss, u0.x, a2[0]);
            a2[1] = fma2(ss, u0.y, a2[1]);
            a2[2] = fma2(ss, u1.x, a2[2]);
            a2[3] = fma2(ss, u1.y, a2[3]);
        }

        // ---- LIF layer 2 ----
        float s2own[8];
        #pragma unroll
        for (int m = 0; m < 4; m++) {
            ull_t mold = m2v[m];
            float mlo, mhi;
            upk2(mold, mlo, mhi);
            float rlo = (mlo > 1.0f) ? 1.0f : 0.0f;
            float rhi = (mhi > 1.0f) ? 1.0f : 0.0f;
            ull_t cur = add2(a2[m], b2own[m]);
            ull_t mb  = mul2(BETA2, mold);
            ull_t tmp = add2(mb, cur);
            ull_t mn  = fma2(pk2(rlo, rhi), NEG2, tmp);
            m2v[m] = mn;
            float nlo, nhi;
            upk2(mn, nlo, nhi);
            s2own[2 * m]     = (nlo > 1.0f) ? 1.0f : 0.0f;
            s2own[2 * m + 1] = (nhi > 1.0f) ? 1.0f : 0.0f;
        }

        // ---- exchange s2 halves ----
        float s2o[8];
        #pragma unroll
        for (int m = 0; m < 4; m++) {
            ull_t sp = pk2(s2own[2 * m], s2own[2 * m + 1]);
            ull_t g  = __shfl_xor_sync(0xFFFFFFFFu, sp, 1);
            upk2(g, s2o[2 * m], s2o[2 * m + 1]);
        }
        float s2all[14];
        #pragma unroll
        for (int i = 0; i < 7; i++) {
            s2all[i]     = q ? s2o[i]   : s2own[i];
            s2all[7 + i] = q ? s2own[i] : s2o[i];
        }

        // ---- layer 3 + LIF 3 ----
        float c3 = 0.0f;
        #pragma unroll
        for (int i = 0; i < HH2; i++) c3 = fmaf(s2all[i], w3s[i], c3);
        float cur3 = __fadd_rn(c3, b3s);

        float r3  = (m3 > 1.0f) ? 1.0f : 0.0f;
        float mb3 = __fmul_rn(0.9f, m3);
        float t3  = __fadd_rn(mb3, cur3);
        m3 = __fsub_rn(t3, r3);

        if (q == 0) out[(size_t)t * BB + e] = m3;

        // ---- rotate double-buffered acc ----
        c0 = n0; c1 = n1; c2 = n2; c3v = n3;
    }
}

extern "C" void kernel_launch(void* const* d_in, const int* in_sizes, int n_in,
                              void* d_out, int out_size) {
    const float* x  = (const float*)d_in[0];
    const float* W1 = (const float*)d_in[1];
    const float* b1 = (const float*)d_in[2];
    const float* W2 = (const float*)d_in[3];
    const float* b2 = (const float*)d_in[4];
    const float* W3 = (const float*)d_in[5];
    const float* b3 = (const float*)d_in[6];
    float* out = (float*)d_out;

    // K1: 2,097,152 element-timesteps, 1 per thread -> 16384 blocks x 128
    snn_layer1_kernel<<<16384, 128>>>(x, W1);

    // K2: 8192 elements, 32 per block (64 threads = 2 threads per element)
    snn_recur_kernel<<<256, 64>>>(b1, W2, b2, W3, b3, out);
}

// round 13
// speedup vs baseline: 1.2091x; 1.0496x over previous
#include <cuda_runtime.h>

// EthanolSNN: 3-layer LIF SNN inference. T=256, B=8192, D=64, H1=28, H2=14.
// Output mem3 [T, B, 1] fp32.
//
// Two-kernel split:
//  K1 (r12): layer-1 accumulations, 4 element-timesteps per thread. The 7
//      warp-uniform weight LDS.128 per k are loaded once and reused for 4
//      elements (r10/r11 paid full crossbar wavefronts for them every element
//      -> 376us crossbar wall). x staged via smem, conflict-free.
//  K2: sequential LIF recurrence with register double-buffered acc loads
//      (UNCHANGED from r11, measured 133us).
//
// Numerics BIT-IDENTICAL to round-5 passing kernel (rel_err 7.44e-4):
//  - dot products: single serial ascending-index FMA chain per neuron
//  - bias added as separate rounded add after the chain
//  - LIF: RN(RN(RN(b*m)+cur)-reset), reset subtract via exact-product fma
//  - threshold m>1 == (m-1)>0 in fp32

typedef unsigned long long ull_t;

#define TT 256
#define BB 8192
#define DD 64
#define HH1 28
#define HH2 14

// scratch: [et][16] ull; et = t*BB+e; half q uses slots [q*8 .. q*8+6]
#define SCRATCH_ULLS (256ULL * 8192ULL * 16ULL)
__device__ ull_t g_cur1[SCRATCH_ULLS];   // 268 MB, module-load allocated

__device__ __forceinline__ ull_t pk2(float lo, float hi) {
    ull_t r;
    asm("mov.b64 %0, {%1, %2};" : "=l"(r) : "f"(lo), "f"(hi));
    return r;
}
__device__ __forceinline__ void upk2(ull_t v, float& lo, float& hi) {
    asm("mov.b64 {%0, %1}, %2;" : "=f"(lo), "=f"(hi) : "l"(v));
}
__device__ __forceinline__ ull_t fma2(ull_t a, ull_t b, ull_t c) {
    ull_t d;
    asm("fma.rn.f32x2 %0, %1, %2, %3;" : "=l"(d) : "l"(a), "l"(b), "l"(c));
    return d;
}
__device__ __forceinline__ ull_t add2(ull_t a, ull_t b) {
    ull_t d;
    asm("add.rn.f32x2 %0, %1, %2;" : "=l"(d) : "l"(a), "l"(b));
    return d;
}
__device__ __forceinline__ ull_t mul2(ull_t a, ull_t b) {
    ull_t d;
    asm("mul.rn.f32x2 %0, %1, %2;" : "=l"(d) : "l"(a), "l"(b));
    return d;
}

// ============================================================================
// Kernel 1 (r12): layer-1 accumulation, 4 element-timesteps per thread.
// Block = 64 threads, covers 256 consecutive et. Thread tid owns rows
// tid, tid+64, tid+128, tid+192 (stride-64 so every pattern stays clean).
//  - stage loads: fully coalesced LDG.128 into smem (rows stride 65 floats)
//  - per k: 7 weight LDS.128 (warp-uniform) loaded ONCE, reused 4x ->
//    crossbar traffic per element cut 4x vs r11
//  - compute LDS.32 x reads: bank (tid+k)%32, conflict-free
// 4 x 14 serial ascending-k fma2 chains (bit-identical numerics).
// ============================================================================
__global__ void __launch_bounds__(64)
snn_layer1_kernel(const float* __restrict__ x, const float* __restrict__ W1)
{
    __shared__ __align__(16) ull_t w1p[DD * 16];   // [k][16]: pairs j=0..13, pad (8KB)
    __shared__ float xs[256 * 65];                 // 256 rows, stride 65 (66.6KB)

    const int tid = threadIdx.x;   // 0..63

    // ---- pack W1 pairs: w1p[k*16+j] = {W1[2j][k], W1[2j+1][k]} ----
    for (int idx = tid; idx < DD * 16; idx += 64) {
        int k = idx >> 4, j = idx & 15;
        float lo = 0.f, hi = 0.f;
        if (j < 14) {
            lo = W1[(2 * j)     * DD + k];
            hi = W1[(2 * j + 1) * DD + k];
        }
        w1p[idx] = pk2(lo, hi);
    }

    // ---- stage this block's 256 x rows (contiguous 64KB of x) ----
    const float4* xg = (const float4*)(x + (size_t)blockIdx.x * (256 * DD));
    #pragma unroll
    for (int r = 0; r < 64; r++) {
        int pos = tid + 64 * r;             // float4 index within 4096-float4 tile
        float4 v = __ldcs(xg + pos);
        int row = pos >> 4;                 // 0..255
        int col = (pos & 15) * 4;           // 0..60
        float* dst = &xs[row * 65 + col];
        dst[0] = v.x; dst[1] = v.y; dst[2] = v.z; dst[3] = v.w;
    }
    __syncthreads();

    // ---- 4 x 14 serial ascending-k fma2 chains ----
    ull_t acc[4][14];
    #pragma unroll
    for (int u = 0; u < 4; u++)
        #pragma unroll
        for (int j = 0; j < 14; j++) acc[u][j] = 0ULL;

    #pragma unroll 1
    for (int k = 0; k < DD; k++) {
        const ulonglong2* wr = (const ulonglong2*)(w1p + k * 16);
        ulonglong2 w01 = wr[0], w23 = wr[1], w45 = wr[2], w67 = wr[3],
                   w89 = wr[4], wab = wr[5], wcd = wr[6];
        #pragma unroll
        for (int u = 0; u < 4; u++) {
            float xv = xs[(tid + 64 * u) * 65 + k];
            ull_t xx = pk2(xv, xv);
            acc[u][0]  = fma2(xx, w01.x, acc[u][0]);
            acc[u][1]  = fma2(xx, w01.y, acc[u][1]);
            acc[u][2]  = fma2(xx, w23.x, acc[u][2]);
            acc[u][3]  = fma2(xx, w23.y, acc[u][3]);
            acc[u][4]  = fma2(xx, w45.x, acc[u][4]);
            acc[u][5]  = fma2(xx, w45.y, acc[u][5]);
            acc[u][6]  = fma2(xx, w67.x, acc[u][6]);
            acc[u][7]  = fma2(xx, w67.y, acc[u][7]);
            acc[u][8]  = fma2(xx, w89.x, acc[u][8]);
            acc[u][9]  = fma2(xx, w89.y, acc[u][9]);
            acc[u][10] = fma2(xx, wab.x, acc[u][10]);
            acc[u][11] = fma2(xx, wab.y, acc[u][11]);
            acc[u][12] = fma2(xx, wcd.x, acc[u][12]);
            acc[u][13] = fma2(xx, wcd.y, acc[u][13]);
        }
    }

    // ---- store to scratch [et][16]: slots 0..6 = pairs 0..6 (q=0 half),
    //      slots 8..14 = pairs 7..13 (q=1 half); aligned STG.128 ----
    #pragma unroll
    for (int u = 0; u < 4; u++) {
        const size_t et = (size_t)blockIdx.x * 256 + tid + 64 * u;
        ulonglong2* d = (ulonglong2*)(g_cur1 + et * 16);
        ulonglong2 p;
        p.x = acc[u][0];  p.y = acc[u][1];  d[0] = p;
        p.x = acc[u][2];  p.y = acc[u][3];  d[1] = p;
        p.x = acc[u][4];  p.y = acc[u][5];  d[2] = p;
        p.x = acc[u][6];  p.y = 0ULL;       d[3] = p;
        p.x = acc[u][7];  p.y = acc[u][8];  d[4] = p;
        p.x = acc[u][9];  p.y = acc[u][10]; d[5] = p;
        p.x = acc[u][11]; p.y = acc[u][12]; d[6] = p;
        p.x = acc[u][13]; p.y = 0ULL;       d[7] = p;
    }
}

// ============================================================================
// Kernel 2: LIF recurrence (r11, UNCHANGED — measured 133us).
// ============================================================================
__global__ void __launch_bounds__(64, 1)
snn_recur_kernel(const float* __restrict__ b1,
                 const float* __restrict__ W2, const float* __restrict__ b2,
                 const float* __restrict__ W3, const float* __restrict__ b3,
                 float* __restrict__ out)
{
    __shared__ __align__(16) ull_t w2p[HH1 * 8];
    __shared__ ull_t b1p[14];
    __shared__ ull_t b2p[8];
    __shared__ float w3s[14];
    __shared__ float b3s;

    const int tid  = threadIdx.x;
    const int lane = tid & 31;
    const int warp = tid >> 5;
    const int p    = lane >> 1;            // element slot within warp (0..15)
    const int q    = lane & 1;             // neuron-half owner
    const int e    = blockIdx.x * 32 + warp * 16 + p;

    for (int idx = tid; idx < HH1 * 8; idx += 64) {
        int i = idx >> 3, r = idx & 7, qq = r >> 2, m = r & 3;
        float lo = (2 * m     < 7) ? W2[(qq * 7 + 2 * m)     * HH1 + i] : 0.f;
        float hi = (2 * m + 1 < 7) ? W2[(qq * 7 + 2 * m + 1) * HH1 + i] : 0.f;
        w2p[idx] = pk2(lo, hi);
    }
    if (tid < 14) {
        int qq = tid / 7, ii = tid - qq * 7;
        b1p[tid] = pk2(b1[qq * 14 + 2 * ii], b1[qq * 14 + 2 * ii + 1]);
        w3s[tid] = W3[tid];
    }
    if (tid < 8) {
        int qq = tid >> 2, m = tid & 3;
        float lo = (2 * m     < 7) ? b2[qq * 7 + 2 * m]     : 0.f;
        float hi = (2 * m + 1 < 7) ? b2[qq * 7 + 2 * m + 1] : 0.f;
        b2p[tid] = pk2(lo, hi);
    }
    if (tid == 0) b3s = b3[0];
    __syncthreads();

    ull_t b1own[7], b2own[4];
    #pragma unroll
    for (int i = 0; i < 7; i++) b1own[i] = b1p[q * 7 + i];
    #pragma unroll
    for (int m = 0; m < 4; m++) b2own[m] = b2p[q * 4 + m];

    const ull_t BETA2 = pk2(0.9f, 0.9f);
    const ull_t NEG2  = pk2(-1.0f, -1.0f);

    ull_t m1v[7], m2v[4];
    #pragma unroll
    for (int i = 0; i < 7; i++) m1v[i] = 0ULL;
    #pragma unroll
    for (int m = 0; m < 4; m++) m2v[m] = 0ULL;
    float m3 = 0.0f;

    const ull_t* cbase = g_cur1 + (size_t)e * 16 + q * 8;
    const size_t cstep = (size_t)BB * 16;

    // ---- preload acc for t=0 ----
    ulonglong2 c0, c1, c2, c3v;
    {
        const ulonglong2* cp = (const ulonglong2*)cbase;
        c0 = cp[0]; c1 = cp[1]; c2 = cp[2]; c3v = cp[3];
    }

    #pragma unroll 1
    for (int t = 0; t < TT; t++) {
        // ---- issue next step's acc loads NOW (consumed next iteration) ----
        const int tn = (t + 1 < TT) ? (t + 1) : t;
        const ulonglong2* np = (const ulonglong2*)(cbase + (size_t)tn * cstep);
        ulonglong2 n0 = np[0], n1 = np[1], n2 = np[2], n3 = np[3];

        // ---- prefetch t+2 into L2 so next iteration's LDG is an L2 hit ----
        if (t + 2 < TT) {
            const char* pf = (const char*)(cbase + (size_t)(t + 2) * cstep);
            asm volatile("prefetch.global.L2 [%0];" :: "l"(pf));
        }

        ull_t acc[7] = {c0.x, c0.y, c1.x, c1.y, c2.x, c2.y, c3v.x};

        // ---- LIF layer 1 (exact rounding sequence) ----
        float s1own[14];
        #pragma unroll
        for (int i = 0; i < 7; i++) {
            ull_t mold = m1v[i];
            float mlo, mhi;
            upk2(mold, mlo, mhi);
            float rlo = (mlo > 1.0f) ? 1.0f : 0.0f;
            float rhi = (mhi > 1.0f) ? 1.0f : 0.0f;
            ull_t cur = add2(acc[i], b1own[i]);
            ull_t mb  = mul2(BETA2, mold);
            ull_t tmp = add2(mb, cur);
            ull_t mn  = fma2(pk2(rlo, rhi), NEG2, tmp);
            m1v[i] = mn;
            float nlo, nhi;
            upk2(mn, nlo, nhi);
            s1own[2 * i]     = (nlo > 1.0f) ? 1.0f : 0.0f;
            s1own[2 * i + 1] = (nhi > 1.0f) ? 1.0f : 0.0f;
        }

        // ---- exchange spike halves across the pair ----
        float s1o[14];
        #pragma unroll
        for (int i = 0; i < 7; i++) {
            ull_t sp = pk2(s1own[2 * i], s1own[2 * i + 1]);
            ull_t g  = __shfl_xor_sync(0xFFFFFFFFu, sp, 1);
            upk2(g, s1o[2 * i], s1o[2 * i + 1]);
        }
        float s1all[28];
        #pragma unroll
        for (int i = 0; i < 14; i++) {
            s1all[i]      = q ? s1o[i]   : s1own[i];
            s1all[14 + i] = q ? s1own[i] : s1o[i];
        }

        // ---- layer 2: serial ascending-i FMA chains ----
        ull_t a2[4];
        #pragma unroll
        for (int m = 0; m < 4; m++) a2[m] = 0ULL;
        #pragma unroll
        for (int i = 0; i < HH1; i++) {
            ull_t ss = pk2(s1all[i], s1all[i]);
            const ulonglong2* wr = (const ulonglong2*)(w2p + (size_t)i * 8 + q * 4);
            ulonglong2 u0 = wr[0], u1 = wr[1];
            a2[0] = fma2(ss, u0.x, a2[0]);
            a2[1] = fma2(ss, u0.y, a2[1]);
            a2[2] = fma2(ss, u1.x, a2[2]);
            a2[3] = fma2(ss, u1.y, a2[3]);
        }

        // ---- LIF layer 2 ----
        float s2own[8];
        #pragma unroll
        for (int m = 0; m < 4; m++) {
            ull_t mold = m2v[m];
            float mlo, mhi;
            upk2(mold, mlo, mhi);
            float rlo = (mlo > 1.0f) ? 1.0f : 0.0f;
            float rhi = (mhi > 1.0f) ? 1.0f : 0.0f;
            ull_t cur = add2(a2[m], b2own[m]);
            ull_t mb  = mul2(BETA2, mold);
            ull_t tmp = add2(mb, cur);
            ull_t mn  = fma2(pk2(rlo, rhi), NEG2, tmp);
            m2v[m] = mn;
            float nlo, nhi;
            upk2(mn, nlo, nhi);
            s2own[2 * m]     = (nlo > 1.0f) ? 1.0f : 0.0f;
            s2own[2 * m + 1] = (nhi > 1.0f) ? 1.0f : 0.0f;
        }

        // ---- exchange s2 halves ----
        float s2o[8];
        #pragma unroll
        for (int m = 0; m < 4; m++) {
            ull_t sp = pk2(s2own[2 * m], s2own[2 * m + 1]);
            ull_t g  = __shfl_xor_sync(0xFFFFFFFFu, sp, 1);
            upk2(g, s2o[2 * m], s2o[2 * m + 1]);
        }
        float s2all[14];
        #pragma unroll
        for (int i = 0; i < 7; i++) {
            s2all[i]     = q ? s2o[i]   : s2own[i];
            s2all[7 + i] = q ? s2own[i] : s2o[i];
        }

        // ---- layer 3 + LIF 3 ----
        float c3 = 0.0f;
        #pragma unroll
        for (int i = 0; i < HH2; i++) c3 = fmaf(s2all[i], w3s[i], c3);
        float cur3 = __fadd_rn(c3, b3s);

        float r3  = (m3 > 1.0f) ? 1.0f : 0.0f;
        float mb3 = __fmul_rn(0.9f, m3);
        float t3  = __fadd_rn(mb3, cur3);
        m3 = __fsub_rn(t3, r3);

        if (q == 0) out[(size_t)t * BB + e] = m3;

        // ---- rotate double-buffered acc ----
        c0 = n0; c1 = n1; c2 = n2; c3v = n3;
    }
}

extern "C" void kernel_launch(void* const* d_in, const int* in_sizes, int n_in,
                              void* d_out, int out_size) {
    const float* x  = (const float*)d_in[0];
    const float* W1 = (const float*)d_in[1];
    const float* b1 = (const float*)d_in[2];
    const float* W2 = (const float*)d_in[3];
    const float* b2 = (const float*)d_in[4];
    const float* W3 = (const float*)d_in[5];
    const float* b3 = (const float*)d_in[6];
    float* out = (float*)d_out;

    // K1: 2,097,152 element-timesteps, 4 per thread -> 8192 blocks x 64
    snn_layer1_kernel<<<8192, 64>>>(x, W1);

    // K2: 8192 elements, 32 per block (64 threads = 2 threads per element)
    snn_recur_kernel<<<256, 64>>>(b1, W2, b2, W3, b3, out);
}